// round 7
// baseline (speedup 1.0000x reference)
#include <cuda_runtime.h>
#include <cuda_bf16.h>
#include <math.h>
#include <stdint.h>

#define N_NODES 500000
#define N_SEG   10000
#define M_PAD   10112            // 79 * 128
#define DIM     256
#define NGATE   1024
#define QSTAR   512
#define NITER   6

typedef __nv_bfloat16 bf16;

// ---------------- scratch (device globals) -----------------------------------
__device__ bf16  g_qstar3[(size_t)M_PAD * 1024];            // row: [hi512 | lo512]
__device__ bf16  g_h3[2 * 3 * (size_t)M_PAD * 512];          // row: [hi256 | lo256]
__device__ float g_c[3 * (size_t)M_PAD * DIM];
__device__ float g_hq[(size_t)M_PAD * DIM];                  // fp32 q for attn
__device__ bf16  g_w3_ih[3][(size_t)NGATE * 1024];           // row: [hi K1 | lo K1]
__device__ bf16  g_w3_hh[3][(size_t)NGATE * 512];            // row: [hi256 | lo256]
__device__ float g_bp[3 * NGATE];
__device__ int   g_start[N_SEG + 1];

// ---------------- helpers ------------------------------------------------------
__device__ __forceinline__ uint32_t smem_u32(const void* p) {
    return (uint32_t)__cvta_generic_to_shared(p);
}
__device__ __forceinline__ void cp16(uint32_t dst, const void* src) {
    asm volatile("cp.async.cg.shared.global [%0], [%1], 16;" :: "r"(dst), "l"(src));
}
#define CP_COMMIT() asm volatile("cp.async.commit_group;" ::: "memory")
#define CP_WAIT(n)  asm volatile("cp.async.wait_group %0;" :: "n"(n) : "memory")

__device__ __forceinline__ void ldsm_x4(uint32_t& r0, uint32_t& r1, uint32_t& r2, uint32_t& r3,
                                        uint32_t addr) {
    asm volatile("ldmatrix.sync.aligned.m8n8.x4.shared.b16 {%0,%1,%2,%3}, [%4];"
        : "=r"(r0), "=r"(r1), "=r"(r2), "=r"(r3) : "r"(addr));
}
__device__ __forceinline__ void mma_bf16(float4& d, const uint32_t* a, uint32_t b0, uint32_t b1) {
    asm volatile(
        "mma.sync.aligned.m16n8k16.row.col.f32.bf16.bf16.f32 "
        "{%0,%1,%2,%3}, {%4,%5,%6,%7}, {%8,%9}, {%0,%1,%2,%3};"
        : "+f"(d.x), "+f"(d.y), "+f"(d.z), "+f"(d.w)
        : "r"(a[0]), "r"(a[1]), "r"(a[2]), "r"(a[3]), "r"(b0), "r"(b1));
}

__device__ __forceinline__ float sigf(float x) { return 1.0f / (1.0f + __expf(-x)); }
__device__ __forceinline__ float tanhfast(float x) { return 2.0f / (1.0f + __expf(-2.0f * x)) - 1.0f; }
__device__ __forceinline__ void bsplit(float x, bf16& hi, bf16& lo) {
    hi = __float2bfloat16(x);
    lo = __float2bfloat16(x - __bfloat162float(hi));
}

// ---------------- prep: split + permute weights -------------------------------
struct PermArgs {
    const float* w_ih[3]; const float* w_hh[3];
    const float* b_ih[3]; const float* b_hh[3];
    int K1[3];
};
__global__ void prep_kernel(PermArgs pa) {
    int l = blockIdx.y;
    int K1 = pa.K1[l];
    bf16* wih = g_w3_ih[l];
    bf16* whh = g_w3_hh[l];
    int n_ih = NGATE * K1, n_hh = NGATE * DIM;
    int total = n_ih + n_hh + NGATE;
    for (int i = blockIdx.x * blockDim.x + threadIdx.x; i < total; i += gridDim.x * blockDim.x) {
        if (i < n_ih) {
            int r = i / K1, k = i - r * K1;
            int u = r >> 2, g = r & 3;
            float v = pa.w_ih[l][(size_t)(g * 256 + u) * K1 + k];
            bf16 hi, lo; bsplit(v, hi, lo);
            wih[(size_t)r * (2 * K1) + k] = hi;
            wih[(size_t)r * (2 * K1) + K1 + k] = lo;
        } else if (i < n_ih + n_hh) {
            int j = i - n_ih;
            int r = j / DIM, k = j - r * DIM;
            int u = r >> 2, g = r & 3;
            float v = pa.w_hh[l][(size_t)(g * 256 + u) * DIM + k];
            bf16 hi, lo; bsplit(v, hi, lo);
            whh[(size_t)r * 512 + k] = hi;
            whh[(size_t)r * 512 + 256 + k] = lo;
        } else {
            int r = i - n_ih - n_hh;
            int u = r >> 2, g = r & 3;
            g_bp[l * NGATE + r] = pa.b_ih[l][g * 256 + u] + pa.b_hh[l][g * 256 + u];
        }
    }
}

// ---------------- init ----------------------------------------------------------
__global__ void init_kernel(const int* __restrict__ seg) {
    size_t gid = (size_t)blockIdx.x * blockDim.x + threadIdx.x;
    size_t stride = (size_t)gridDim.x * blockDim.x;
    const size_t nq = (size_t)M_PAD * 1024;
    const size_t nh = (size_t)2 * 3 * M_PAD * 512;
    const size_t nc = (size_t)3 * M_PAD * DIM;
    bf16 z = __float2bfloat16(0.0f);
    for (size_t i = gid; i < nq; i += stride) g_qstar3[i] = z;
    for (size_t i = gid; i < nh; i += stride) g_h3[i] = z;
    for (size_t i = gid; i < nc; i += stride) g_c[i] = 0.0f;
    if (gid <= N_SEG) {
        int s = (int)gid;
        int lo = 0, hi = N_NODES;
        while (lo < hi) { int mid = (lo + hi) >> 1; if (seg[mid] < s) lo = mid + 1; else hi = mid; }
        g_start[s] = lo;
    }
}

// ---------------- HMMA GEMM + fused LSTM cell ----------------------------------
// gates = sum over 6 passes {(Ahi,Whi),(Alo,Whi),(Ahi,Wlo)} x {ih, hh}.
// 3-stage cp.async pipeline, one __syncthreads per chunk.
#define SM_BUF   16384
#define STAGE_SZ 32768
#define SMEM_GE  (3 * STAGE_SZ)

template<int K1>
__global__ __launch_bounds__(256, 2)
void gemm_lstm_mma(const bf16* __restrict__ A1, const bf16* __restrict__ W1,
                   const bf16* __restrict__ A2, const bf16* __restrict__ W2,
                   const float* __restrict__ bias,
                   float* __restrict__ c, bf16* __restrict__ h3out,
                   float* __restrict__ hq, int write_q) {
    extern __shared__ __align__(128) char smem[];
    const uint32_t sbase = smem_u32(smem);
    const int tid = threadIdx.x;
    const int lane = tid & 31;
    const int wid = tid >> 5;
    const int warp_m = wid & 3;
    const int warp_n = wid >> 2;
    const int bm = blockIdx.x * 128;
    const int bn = blockIdx.y * 128;

    constexpr int C1 = K1 / 64;          // chunks per ih term
    constexpr int NC = 3 * C1 + 12;      // total chunks

    // ---- loop-invariant loader state ----
    // thread handles rows r(q) = (tid>>3) + 32q, segment sg = tid&7 (fixed)
    const int r0 = tid >> 3;
    const int sg = tid & 7;
    const uint32_t so0 = (uint32_t)(r0 * 128 + ((sg * 16) ^ ((r0 & 7) << 4)));
    const bf16* a1p = A1 + (size_t)(bm + r0) * (2 * K1) + sg * 8;
    const bf16* w1p = W1 + (size_t)(bn + r0) * (2 * K1) + sg * 8;
    const bf16* a2p = A2 + (size_t)(bm + r0) * 512 + sg * 8;
    const bf16* w2p = W2 + (size_t)(bn + r0) * 512 + sg * 8;

    // issue all 8 cp.async for chunk g into stage st
    auto load_chunk = [&](int g, int st) {
        int ao, wo;
        const bool ih = (g < 3 * C1);
        if (ih) {
            int p = g / C1, ci = g - p * C1;
            ao = ((p == 1) ? K1 : 0) + ci * 64;
            wo = ((p == 2) ? K1 : 0) + ci * 64;
        } else {
            int gg = g - 3 * C1;
            int p = gg >> 2, ci = gg & 3;
            ao = ((p == 1) ? 256 : 0) + ci * 64;
            wo = ((p == 2) ? 256 : 0) + ci * 64;
        }
        const uint32_t sA = sbase + st * STAGE_SZ + so0;
        const uint32_t sB = sA + SM_BUF;
#pragma unroll
        for (int q = 0; q < 4; q++) {
            constexpr size_t ST1 = (size_t)32 * 2 * K1;   // row stride * 32, compile-time
            constexpr size_t ST2 = (size_t)32 * 512;
            const size_t o1 = q * ST1, o2 = q * ST2;
            const uint32_t sq = q * 4096;
            if (ih) {
                cp16(sA + sq, a1p + o1 + ao);
                cp16(sB + sq, w1p + o1 + wo);
            } else {
                cp16(sA + sq, a2p + o2 + ao);
                cp16(sB + sq, w2p + o2 + wo);
            }
        }
        CP_COMMIT();
    };

    float4 acc[2][8];
#pragma unroll
    for (int i = 0; i < 2; i++)
#pragma unroll
        for (int j = 0; j < 8; j++) acc[i][j] = make_float4(0.f, 0.f, 0.f, 0.f);

    load_chunk(0, 0);
    load_chunk(1, 1);

    // hoisted ldmatrix addressing: addr = stagebase + base + ((ks*32) ^ xc)
    const int koff = (lane >> 4) * 16;
    uint32_t a_base[2], a_xc[2], b_base[4], b_xc[4];
#pragma unroll
    for (int tm = 0; tm < 2; tm++) {
        int row = warp_m * 32 + tm * 16 + (lane & 15);
        a_base[tm] = sbase + row * 128;
        a_xc[tm] = (uint32_t)(koff ^ ((row & 7) << 4));
    }
#pragma unroll
    for (int tn2 = 0; tn2 < 4; tn2++) {
        int row = warp_n * 64 + tn2 * 16 + (lane & 15);
        b_base[tn2] = sbase + SM_BUF + row * 128;
        b_xc[tn2] = (uint32_t)(koff ^ ((row & 7) << 4));
    }

    int st_cur = 0, st_nxt = 2;   // stage of chunk g; stage for chunk g+2

#pragma unroll 1
    for (int g = 0; g < NC; g++) {
        if (g + 1 < NC) { CP_WAIT(1); } else { CP_WAIT(0); }
        __syncthreads();                       // single barrier per chunk

        if (g + 2 < NC) load_chunk(g + 2, st_nxt);

        const uint32_t stoff = st_cur * STAGE_SZ;
#pragma unroll
        for (int ks = 0; ks < 4; ks++) {
            uint32_t a[2][4];
#pragma unroll
            for (int tm = 0; tm < 2; tm++)
                ldsm_x4(a[tm][0], a[tm][1], a[tm][2], a[tm][3],
                        a_base[tm] + stoff + ((uint32_t)(ks * 32) ^ a_xc[tm]));
            uint32_t b[4][4];
#pragma unroll
            for (int tn2 = 0; tn2 < 4; tn2++)
                ldsm_x4(b[tn2][0], b[tn2][1], b[tn2][2], b[tn2][3],
                        b_base[tn2] + stoff + ((uint32_t)(ks * 32) ^ b_xc[tn2]));
#pragma unroll
            for (int tm = 0; tm < 2; tm++)
#pragma unroll
                for (int tn2 = 0; tn2 < 4; tn2++) {
                    mma_bf16(acc[tm][tn2 * 2 + 0], a[tm], b[tn2][0], b[tn2][2]);
                    mma_bf16(acc[tm][tn2 * 2 + 1], a[tm], b[tn2][1], b[tn2][3]);
                }
        }

        st_cur = (st_cur == 2) ? 0 : st_cur + 1;
        st_nxt = (st_nxt == 2) ? 0 : st_nxt + 1;
    }

    // ---- fused LSTM epilogue ----
    const bool even = !(lane & 1);
#pragma unroll
    for (int tm = 0; tm < 2; tm++) {
#pragma unroll
        for (int tn = 0; tn < 8; tn++) {
            float4 d = acc[tm][tn];
            float e0 = __shfl_xor_sync(0xffffffffu, d.x, 1);
            float e1 = __shfl_xor_sync(0xffffffffu, d.y, 1);
            float e2 = __shfl_xor_sync(0xffffffffu, d.z, 1);
            float e3 = __shfl_xor_sync(0xffffffffu, d.w, 1);
            if (even) {
                int col = bn + warp_n * 64 + tn * 8 + (lane & 3) * 2;
                int u = col >> 2;
                float4 bi = *(const float4*)&bias[col];
                int rA = bm + warp_m * 32 + tm * 16 + (lane >> 2);
#pragma unroll
                for (int rh = 0; rh < 2; rh++) {
                    int row = rA + rh * 8;
                    float gi = (rh ? d.z : d.x) + bi.x;
                    float gf = (rh ? d.w : d.y) + bi.y;
                    float gg = (rh ? e2 : e0) + bi.z;
                    float go = (rh ? e3 : e1) + bi.w;
                    size_t cidx = (size_t)row * DIM + u;
                    float cn = sigf(gf) * c[cidx] + sigf(gi) * tanhfast(gg);
                    c[cidx] = cn;
                    float hn = sigf(go) * tanhfast(cn);
                    bf16 hh, hl; bsplit(hn, hh, hl);
                    h3out[(size_t)row * 512 + u] = hh;
                    h3out[(size_t)row * 512 + 256 + u] = hl;
                    if (write_q) hq[(size_t)row * DIM + u] = hn;
                }
            }
        }
    }
}

// ---------------- fused attention: online softmax per segment ------------------
__global__ void attn_kernel(const float* __restrict__ feats,
                            const float* __restrict__ q,
                            float* __restrict__ out) {
    const int s = blockIdx.x;
    const int lo = g_start[s], hi = g_start[s + 1];
    const int w = threadIdx.x >> 5;
    const int lane = threadIdx.x & 31;

    __shared__ float sm_m[8];
    __shared__ float sm_s[8];
    __shared__ float sm_r[8][256];

    const float4* qv = (const float4*)(q + (size_t)s * DIM);
    float4 q0 = qv[lane];
    float4 q1 = qv[lane + 32];

    float m = -INFINITY, ssum = 0.0f;
    float4 r0 = make_float4(0.f, 0.f, 0.f, 0.f);
    float4 r1 = make_float4(0.f, 0.f, 0.f, 0.f);

    for (int n = lo + w; n < hi; n += 8) {
        const float4* f = (const float4*)(feats + (size_t)n * DIM);
        float4 f0 = f[lane];
        float4 f1 = f[lane + 32];
        float d = f0.x * q0.x + f0.y * q0.y + f0.z * q0.z + f0.w * q0.w
                + f1.x * q1.x + f1.y * q1.y + f1.z * q1.z + f1.w * q1.w;
#pragma unroll
        for (int o = 16; o > 0; o >>= 1) d += __shfl_xor_sync(0xffffffffu, d, o);

        float mn = fmaxf(m, d);
        float sc = __expf(m - mn);
        float p  = __expf(d - mn);
        ssum = ssum * sc + p;
        r0.x = r0.x * sc + p * f0.x;  r0.y = r0.y * sc + p * f0.y;
        r0.z = r0.z * sc + p * f0.z;  r0.w = r0.w * sc + p * f0.w;
        r1.x = r1.x * sc + p * f1.x;  r1.y = r1.y * sc + p * f1.y;
        r1.z = r1.z * sc + p * f1.z;  r1.w = r1.w * sc + p * f1.w;
        m = mn;
    }

    if (lane == 0) { sm_m[w] = m; sm_s[w] = ssum; }
    *(float4*)&sm_r[w][4 * lane]       = r0;
    *(float4*)&sm_r[w][128 + 4 * lane] = r1;
    __syncthreads();

    const int t = threadIdx.x;
    float M = -INFINITY;
#pragma unroll
    for (int k = 0; k < 8; k++)
        if (sm_s[k] > 0.0f) M = fmaxf(M, sm_m[k]);
    float S = 0.0f, R = 0.0f;
#pragma unroll
    for (int k = 0; k < 8; k++) {
        if (sm_s[k] > 0.0f) {
            float sc = __expf(sm_m[k] - M);
            S += sm_s[k] * sc;
            R += sm_r[k][t] * sc;
        }
    }
    float rv = (S > 0.0f) ? R / S : 0.0f;
    float qv_ = q[(size_t)s * DIM + t];
    out[(size_t)s * QSTAR + t]       = qv_;
    out[(size_t)s * QSTAR + DIM + t] = rv;

    bf16 qh, ql, rh, rl;
    bsplit(qv_, qh, ql); bsplit(rv, rh, rl);
    bf16* qs = g_qstar3 + (size_t)s * 1024;
    qs[t]             = qh;
    qs[256 + t]       = rh;
    qs[512 + t]       = ql;
    qs[512 + 256 + t] = rl;
}

// ---------------- host orchestration -------------------------------------------
extern "C" void kernel_launch(void* const* d_in, const int* in_sizes, int n_in,
                              void* d_out, int out_size) {
    const float* feats = (const float*)d_in[0];
    const int* seg = (const int*)d_in[1];
    float* out = (float*)d_out;

    PermArgs pa;
    for (int l = 0; l < 3; l++) {
        pa.w_ih[l] = (const float*)d_in[2 + 4 * l];
        pa.w_hh[l] = (const float*)d_in[3 + 4 * l];
        pa.b_ih[l] = (const float*)d_in[4 + 4 * l];
        pa.b_hh[l] = (const float*)d_in[5 + 4 * l];
        pa.K1[l] = (l == 0) ? QSTAR : DIM;
    }

    bf16 *qs3, *h3; float *c, *hq, *bp; bf16 *wih[3], *whh[3];
    cudaGetSymbolAddress((void**)&qs3, g_qstar3);
    cudaGetSymbolAddress((void**)&h3, g_h3);
    cudaGetSymbolAddress((void**)&c, g_c);
    cudaGetSymbolAddress((void**)&hq, g_hq);
    cudaGetSymbolAddress((void**)&bp, g_bp);
    {
        bf16* base_ih; bf16* base_hh;
        cudaGetSymbolAddress((void**)&base_ih, g_w3_ih);
        cudaGetSymbolAddress((void**)&base_hh, g_w3_hh);
        for (int l = 0; l < 3; l++) {
            wih[l] = base_ih + (size_t)l * NGATE * 1024;
            whh[l] = base_hh + (size_t)l * NGATE * 512;
        }
    }

    cudaFuncSetAttribute(gemm_lstm_mma<512>, cudaFuncAttributeMaxDynamicSharedMemorySize, SMEM_GE);
    cudaFuncSetAttribute(gemm_lstm_mma<256>, cudaFuncAttributeMaxDynamicSharedMemorySize, SMEM_GE);

    dim3 pgrid(256, 3);
    prep_kernel<<<pgrid, 256>>>(pa);
    init_kernel<<<1184, 256>>>(seg);

    const size_t SD3 = (size_t)M_PAD * 512;
    dim3 ggrid(M_PAD / 128, NGATE / 128);

    for (int it = 0; it < NITER; it++) {
        bf16* h3in  = h3 + (size_t)(it & 1) * 3 * SD3;
        bf16* h3out = h3 + (size_t)((it + 1) & 1) * 3 * SD3;
        for (int l = 0; l < 3; l++) {
            const bf16* A1 = (l == 0) ? qs3 : (h3out + (size_t)(l - 1) * SD3);
            if (l == 0) {
                gemm_lstm_mma<512><<<ggrid, 256, SMEM_GE>>>(
                    A1, wih[l], h3in + (size_t)l * SD3, whh[l],
                    bp + l * NGATE, c + (size_t)l * M_PAD * DIM,
                    h3out + (size_t)l * SD3, hq, 0);
            } else {
                gemm_lstm_mma<256><<<ggrid, 256, SMEM_GE>>>(
                    A1, wih[l], h3in + (size_t)l * SD3, whh[l],
                    bp + l * NGATE, c + (size_t)l * M_PAD * DIM,
                    h3out + (size_t)l * SD3, hq, (l == 2) ? 1 : 0);
            }
        }
        attn_kernel<<<N_SEG, 256>>>(feats, hq, out);
    }
}

// round 9
// speedup vs baseline: 1.5239x; 1.5239x over previous
#include <cuda_runtime.h>
#include <cuda_fp16.h>
#include <math.h>
#include <stdint.h>

#define N_NODES 500000
#define N_SEG   10000
#define M_PAD   10112            // 79 * 128
#define DIM     256
#define NGATE   1024
#define QSTAR   512
#define NITER   6

// ---------------- scratch (device globals) -----------------------------------
__device__ half  g_qstar[(size_t)M_PAD * 512];              // fp16 [q|r]
__device__ half  g_hh[2 * 3 * (size_t)M_PAD * 256];          // fp16 h, ping-pong x 3 layers
__device__ float g_c[3 * (size_t)M_PAD * DIM];
__device__ float g_hq[(size_t)M_PAD * DIM];                  // fp32 q for attn
__device__ half  g_w_ih[3][(size_t)NGATE * 512];             // permuted fp16 (K1<=512)
__device__ half  g_w_hh[3][(size_t)NGATE * 256];
__device__ float g_bp[3 * NGATE];
__device__ int   g_start[N_SEG + 1];

// ---------------- helpers ------------------------------------------------------
__device__ __forceinline__ uint32_t smem_u32(const void* p) {
    return (uint32_t)__cvta_generic_to_shared(p);
}
__device__ __forceinline__ void cp16(uint32_t dst, const void* src) {
    asm volatile("cp.async.cg.shared.global [%0], [%1], 16;" :: "r"(dst), "l"(src));
}
#define CP_COMMIT() asm volatile("cp.async.commit_group;" ::: "memory")
#define CP_WAIT(n)  asm volatile("cp.async.wait_group %0;" :: "n"(n) : "memory")

__device__ __forceinline__ void ldsm_x4(uint32_t& r0, uint32_t& r1, uint32_t& r2, uint32_t& r3,
                                        uint32_t addr) {
    asm volatile("ldmatrix.sync.aligned.m8n8.x4.shared.b16 {%0,%1,%2,%3}, [%4];"
        : "=r"(r0), "=r"(r1), "=r"(r2), "=r"(r3) : "r"(addr));
}
__device__ __forceinline__ void mma_f16(float4& d, const uint32_t* a, uint32_t b0, uint32_t b1) {
    asm volatile(
        "mma.sync.aligned.m16n8k16.row.col.f32.f16.f16.f32 "
        "{%0,%1,%2,%3}, {%4,%5,%6,%7}, {%8,%9}, {%0,%1,%2,%3};"
        : "+f"(d.x), "+f"(d.y), "+f"(d.z), "+f"(d.w)
        : "r"(a[0]), "r"(a[1]), "r"(a[2]), "r"(a[3]), "r"(b0), "r"(b1));
}

__device__ __forceinline__ float sigf(float x) { return 1.0f / (1.0f + __expf(-x)); }
__device__ __forceinline__ float tanhfast(float x) { return 2.0f / (1.0f + __expf(-2.0f * x)) - 1.0f; }

// ---------------- prep: convert + permute weights to gate-interleaved fp16 -----
struct PermArgs {
    const float* w_ih[3]; const float* w_hh[3];
    const float* b_ih[3]; const float* b_hh[3];
    int K1[3];
};
__global__ void prep_kernel(PermArgs pa) {
    int l = blockIdx.y;
    int K1 = pa.K1[l];
    half* wih = g_w_ih[l];
    half* whh = g_w_hh[l];
    int n_ih = NGATE * K1, n_hh = NGATE * DIM;
    int total = n_ih + n_hh + NGATE;
    for (int i = blockIdx.x * blockDim.x + threadIdx.x; i < total; i += gridDim.x * blockDim.x) {
        if (i < n_ih) {
            int r = i / K1, k = i - r * K1;
            int u = r >> 2, g = r & 3;
            wih[i] = __float2half_rn(pa.w_ih[l][(size_t)(g * 256 + u) * K1 + k]);
        } else if (i < n_ih + n_hh) {
            int j = i - n_ih;
            int r = j / DIM, k = j - r * DIM;
            int u = r >> 2, g = r & 3;
            whh[j] = __float2half_rn(pa.w_hh[l][(size_t)(g * 256 + u) * DIM + k]);
        } else {
            int r = i - n_ih - n_hh;
            int u = r >> 2, g = r & 3;
            g_bp[l * NGATE + r] = pa.b_ih[l][g * 256 + u] + pa.b_hh[l][g * 256 + u];
        }
    }
}

// ---------------- init ----------------------------------------------------------
__global__ void init_kernel(const int* __restrict__ seg) {
    size_t gid = (size_t)blockIdx.x * blockDim.x + threadIdx.x;
    size_t stride = (size_t)gridDim.x * blockDim.x;
    const size_t nq = (size_t)M_PAD * 512;
    const size_t nh = (size_t)2 * 3 * M_PAD * 256;
    const size_t nc = (size_t)3 * M_PAD * DIM;
    half z = __float2half_rn(0.0f);
    for (size_t i = gid; i < nq; i += stride) g_qstar[i] = z;
    for (size_t i = gid; i < nh; i += stride) g_hh[i] = z;
    for (size_t i = gid; i < nc; i += stride) g_c[i] = 0.0f;
    if (gid <= N_SEG) {
        int s = (int)gid;
        int lo = 0, hi = N_NODES;
        while (lo < hi) { int mid = (lo + hi) >> 1; if (seg[mid] < s) lo = mid + 1; else hi = mid; }
        g_start[s] = lo;
    }
}

// ---------------- fp16 HMMA GEMM + fused LSTM cell ------------------------------
// gates = A1 @ W1^T + A2 @ W2^T (+bias), single fp16 pass, fp32 accumulate.
// 3-stage cp.async pipeline, one __syncthreads per chunk.
#define SM_BUF   16384
#define STAGE_SZ 32768
#define SMEM_GE  (3 * STAGE_SZ)

template<int K1>
__global__ __launch_bounds__(256, 2)
void gemm_lstm_mma(const half* __restrict__ A1, const half* __restrict__ W1,
                   const half* __restrict__ A2, const half* __restrict__ W2,
                   const float* __restrict__ bias,
                   float* __restrict__ c, half* __restrict__ hout,
                   float* __restrict__ hq, int write_q) {
    extern __shared__ __align__(128) char smem[];
    const uint32_t sbase = smem_u32(smem);
    const int tid = threadIdx.x;
    const int lane = tid & 31;
    const int wid = tid >> 5;
    const int warp_m = wid & 3;
    const int warp_n = wid >> 2;
    const int bm = blockIdx.x * 128;
    const int bn = blockIdx.y * 128;

    constexpr int C1 = K1 / 64;          // ih chunks (8 or 4)
    constexpr int NC = C1 + 4;           // + hh chunks (K2=256)

    // loop-invariant loader state: rows r(q) = (tid>>3) + 32q, segment sg = tid&7
    const int r0 = tid >> 3;
    const int sg = tid & 7;
    const uint32_t so0 = (uint32_t)(r0 * 128 + ((sg * 16) ^ ((r0 & 7) << 4)));
    const half* a1p = A1 + (size_t)(bm + r0) * K1 + sg * 8;
    const half* w1p = W1 + (size_t)(bn + r0) * K1 + sg * 8;
    const half* a2p = A2 + (size_t)(bm + r0) * 256 + sg * 8;
    const half* w2p = W2 + (size_t)(bn + r0) * 256 + sg * 8;

    auto load_chunk = [&](int g, int st) {
        const uint32_t sA = sbase + st * STAGE_SZ + so0;
        const uint32_t sB = sA + SM_BUF;
        if (g < C1) {
            const int off = g * 64;
#pragma unroll
            for (int q = 0; q < 4; q++) {
                constexpr size_t ST = (size_t)32 * K1;
                cp16(sA + q * 4096, a1p + q * ST + off);
                cp16(sB + q * 4096, w1p + q * ST + off);
            }
        } else {
            const int off = (g - C1) * 64;
#pragma unroll
            for (int q = 0; q < 4; q++) {
                constexpr size_t ST = (size_t)32 * 256;
                cp16(sA + q * 4096, a2p + q * ST + off);
                cp16(sB + q * 4096, w2p + q * ST + off);
            }
        }
        CP_COMMIT();
    };

    float4 acc[2][8];
#pragma unroll
    for (int i = 0; i < 2; i++)
#pragma unroll
        for (int j = 0; j < 8; j++) acc[i][j] = make_float4(0.f, 0.f, 0.f, 0.f);

    load_chunk(0, 0);
    load_chunk(1, 1);

    // hoisted ldmatrix addressing: addr = stagebase + base + ((ks*32) ^ xc)
    const int koff = (lane >> 4) * 16;
    uint32_t a_base[2], a_xc[2], b_base[4], b_xc[4];
#pragma unroll
    for (int tm = 0; tm < 2; tm++) {
        int row = warp_m * 32 + tm * 16 + (lane & 15);
        a_base[tm] = sbase + row * 128;
        a_xc[tm] = (uint32_t)(koff ^ ((row & 7) << 4));
    }
#pragma unroll
    for (int tn2 = 0; tn2 < 4; tn2++) {
        int row = warp_n * 64 + tn2 * 16 + (lane & 15);
        b_base[tn2] = sbase + SM_BUF + row * 128;
        b_xc[tn2] = (uint32_t)(koff ^ ((row & 7) << 4));
    }

    int st_cur = 0, st_nxt = 2;

#pragma unroll 1
    for (int g = 0; g < NC; g++) {
        if (g + 1 < NC) { CP_WAIT(1); } else { CP_WAIT(0); }
        __syncthreads();

        if (g + 2 < NC) load_chunk(g + 2, st_nxt);

        const uint32_t stoff = st_cur * STAGE_SZ;
#pragma unroll
        for (int ks = 0; ks < 4; ks++) {
            uint32_t a[2][4];
#pragma unroll
            for (int tm = 0; tm < 2; tm++)
                ldsm_x4(a[tm][0], a[tm][1], a[tm][2], a[tm][3],
                        a_base[tm] + stoff + ((uint32_t)(ks * 32) ^ a_xc[tm]));
            uint32_t b[4][4];
#pragma unroll
            for (int tn2 = 0; tn2 < 4; tn2++)
                ldsm_x4(b[tn2][0], b[tn2][1], b[tn2][2], b[tn2][3],
                        b_base[tn2] + stoff + ((uint32_t)(ks * 32) ^ b_xc[tn2]));
#pragma unroll
            for (int tm = 0; tm < 2; tm++)
#pragma unroll
                for (int tn2 = 0; tn2 < 4; tn2++) {
                    mma_f16(acc[tm][tn2 * 2 + 0], a[tm], b[tn2][0], b[tn2][2]);
                    mma_f16(acc[tm][tn2 * 2 + 1], a[tm], b[tn2][1], b[tn2][3]);
                }
        }

        st_cur = (st_cur == 2) ? 0 : st_cur + 1;
        st_nxt = (st_nxt == 2) ? 0 : st_nxt + 1;
    }

    // ---- fused LSTM epilogue ----
    const bool even = !(lane & 1);
#pragma unroll
    for (int tm = 0; tm < 2; tm++) {
#pragma unroll
        for (int tn = 0; tn < 8; tn++) {
            float4 d = acc[tm][tn];
            float e0 = __shfl_xor_sync(0xffffffffu, d.x, 1);
            float e1 = __shfl_xor_sync(0xffffffffu, d.y, 1);
            float e2 = __shfl_xor_sync(0xffffffffu, d.z, 1);
            float e3 = __shfl_xor_sync(0xffffffffu, d.w, 1);
            if (even) {
                int col = bn + warp_n * 64 + tn * 8 + (lane & 3) * 2;
                int u = col >> 2;
                float4 bi = *(const float4*)&bias[col];
                int rA = bm + warp_m * 32 + tm * 16 + (lane >> 2);
#pragma unroll
                for (int rh = 0; rh < 2; rh++) {
                    int row = rA + rh * 8;
                    float gi = (rh ? d.z : d.x) + bi.x;
                    float gf = (rh ? d.w : d.y) + bi.y;
                    float gg = (rh ? e2 : e0) + bi.z;
                    float go = (rh ? e3 : e1) + bi.w;
                    size_t cidx = (size_t)row * DIM + u;
                    float cn = sigf(gf) * c[cidx] + sigf(gi) * tanhfast(gg);
                    c[cidx] = cn;
                    float hn = sigf(go) * tanhfast(cn);
                    hout[(size_t)row * 256 + u] = __float2half_rn(hn);
                    if (write_q) hq[(size_t)row * DIM + u] = hn;
                }
            }
        }
    }
}

// ---------------- fused attention: online softmax per segment ------------------
__global__ void attn_kernel(const float* __restrict__ feats,
                            const float* __restrict__ q,
                            float* __restrict__ out) {
    const int s = blockIdx.x;
    const int lo = g_start[s], hi = g_start[s + 1];
    const int w = threadIdx.x >> 5;
    const int lane = threadIdx.x & 31;

    __shared__ float sm_m[8];
    __shared__ float sm_s[8];
    __shared__ float sm_r[8][256];

    const float4* qv = (const float4*)(q + (size_t)s * DIM);
    float4 q0 = qv[lane];
    float4 q1 = qv[lane + 32];

    float m = -INFINITY, ssum = 0.0f;
    float4 r0 = make_float4(0.f, 0.f, 0.f, 0.f);
    float4 r1 = make_float4(0.f, 0.f, 0.f, 0.f);

    for (int n = lo + w; n < hi; n += 8) {
        const float4* f = (const float4*)(feats + (size_t)n * DIM);
        float4 f0 = f[lane];
        float4 f1 = f[lane + 32];
        float d = f0.x * q0.x + f0.y * q0.y + f0.z * q0.z + f0.w * q0.w
                + f1.x * q1.x + f1.y * q1.y + f1.z * q1.z + f1.w * q1.w;
#pragma unroll
        for (int o = 16; o > 0; o >>= 1) d += __shfl_xor_sync(0xffffffffu, d, o);

        float mn = fmaxf(m, d);
        float sc = __expf(m - mn);
        float p  = __expf(d - mn);
        ssum = ssum * sc + p;
        r0.x = r0.x * sc + p * f0.x;  r0.y = r0.y * sc + p * f0.y;
        r0.z = r0.z * sc + p * f0.z;  r0.w = r0.w * sc + p * f0.w;
        r1.x = r1.x * sc + p * f1.x;  r1.y = r1.y * sc + p * f1.y;
        r1.z = r1.z * sc + p * f1.z;  r1.w = r1.w * sc + p * f1.w;
        m = mn;
    }

    if (lane == 0) { sm_m[w] = m; sm_s[w] = ssum; }
    *(float4*)&sm_r[w][4 * lane]       = r0;
    *(float4*)&sm_r[w][128 + 4 * lane] = r1;
    __syncthreads();

    const int t = threadIdx.x;
    float M = -INFINITY;
#pragma unroll
    for (int k = 0; k < 8; k++)
        if (sm_s[k] > 0.0f) M = fmaxf(M, sm_m[k]);
    float S = 0.0f, R = 0.0f;
#pragma unroll
    for (int k = 0; k < 8; k++) {
        if (sm_s[k] > 0.0f) {
            float sc = __expf(sm_m[k] - M);
            S += sm_s[k] * sc;
            R += sm_r[k][t] * sc;
        }
    }
    float rv = (S > 0.0f) ? R / S : 0.0f;
    float qv_ = q[(size_t)s * DIM + t];
    out[(size_t)s * QSTAR + t]       = qv_;
    out[(size_t)s * QSTAR + DIM + t] = rv;

    half* qs = g_qstar + (size_t)s * 512;
    qs[t]       = __float2half_rn(qv_);
    qs[256 + t] = __float2half_rn(rv);
}

// ---------------- host orchestration -------------------------------------------
extern "C" void kernel_launch(void* const* d_in, const int* in_sizes, int n_in,
                              void* d_out, int out_size) {
    const float* feats = (const float*)d_in[0];
    const int* seg = (const int*)d_in[1];
    float* out = (float*)d_out;

    PermArgs pa;
    for (int l = 0; l < 3; l++) {
        pa.w_ih[l] = (const float*)d_in[2 + 4 * l];
        pa.w_hh[l] = (const float*)d_in[3 + 4 * l];
        pa.b_ih[l] = (const float*)d_in[4 + 4 * l];
        pa.b_hh[l] = (const float*)d_in[5 + 4 * l];
        pa.K1[l] = (l == 0) ? QSTAR : DIM;
    }

    half *qs, *hh; float *c, *hq, *bp; half *wih[3], *whh[3];
    cudaGetSymbolAddress((void**)&qs, g_qstar);
    cudaGetSymbolAddress((void**)&hh, g_hh);
    cudaGetSymbolAddress((void**)&c, g_c);
    cudaGetSymbolAddress((void**)&hq, g_hq);
    cudaGetSymbolAddress((void**)&bp, g_bp);
    {
        half* base_ih; half* base_hh;
        cudaGetSymbolAddress((void**)&base_ih, g_w_ih);
        cudaGetSymbolAddress((void**)&base_hh, g_w_hh);
        for (int l = 0; l < 3; l++) {
            wih[l] = base_ih + (size_t)l * NGATE * 512;
            whh[l] = base_hh + (size_t)l * NGATE * 256;
        }
    }

    cudaFuncSetAttribute(gemm_lstm_mma<512>, cudaFuncAttributeMaxDynamicSharedMemorySize, SMEM_GE);
    cudaFuncSetAttribute(gemm_lstm_mma<256>, cudaFuncAttributeMaxDynamicSharedMemorySize, SMEM_GE);

    dim3 pgrid(256, 3);
    prep_kernel<<<pgrid, 256>>>(pa);
    init_kernel<<<1184, 256>>>(seg);

    const size_t SDH = (size_t)M_PAD * 256;   // h layer stride
    dim3 ggrid(M_PAD / 128, NGATE / 128);

    for (int it = 0; it < NITER; it++) {
        half* hin  = hh + (size_t)(it & 1) * 3 * SDH;
        half* hout = hh + (size_t)((it + 1) & 1) * 3 * SDH;
        for (int l = 0; l < 3; l++) {
            const half* A1 = (l == 0) ? qs : (hout + (size_t)(l - 1) * SDH);
            if (l == 0) {
                gemm_lstm_mma<512><<<ggrid, 256, SMEM_GE>>>(
                    A1, wih[l], hin + (size_t)l * SDH, whh[l],
                    bp + l * NGATE, c + (size_t)l * M_PAD * DIM,
                    hout + (size_t)l * SDH, hq, 0);
            } else {
                gemm_lstm_mma<256><<<ggrid, 256, SMEM_GE>>>(
                    A1, wih[l], hin + (size_t)l * SDH, whh[l],
                    bp + l * NGATE, c + (size_t)l * M_PAD * DIM,
                    hout + (size_t)l * SDH, hq, (l == 2) ? 1 : 0);
            }
        }
        attn_kernel<<<N_SEG, 256>>>(feats, hq, out);
    }
}